// round 1
// baseline (speedup 1.0000x reference)
#include <cuda_runtime.h>
#include <cuda_bf16.h>
#include <math.h>

// Problem constants (fixed by setup_inputs): B=2048, K=128, D=256
#define BB 2048
#define KK 128
#define DD 256

#define BT 64      // b-rows per block
#define KT 32      // k-cols per block
#define PITCH 260  // smem row pitch in floats (256 + 4) -> conflict-free LDS.128
#define NTHREADS 256

// logits[b][k] = 2*an_k * asinh( 2*(S*xa + T*ya)*den / (den^2 - (S^2*x2 + 2*S*T*xy + T^2*y2)) )
// where g = z_k . y_b, xy = s_k*g, ya = t_k*g, S = 1+2xy+y2, den = 1+2xy+x2*y2, T = 1-x2

__global__ void __launch_bounds__(NTHREADS, 1)
mlr_logits_kernel(const float* __restrict__ Y,   // output_before (B, D)
                  const float* __restrict__ Z,   // z_mlr (K, D)
                  const float* __restrict__ R,   // mlr_r (K, 1)
                  float* __restrict__ Out)       // (B, K)
{
    extern __shared__ float smem[];
    float* ysm   = smem;                    // BT * PITCH
    float* zsm   = ysm + BT * PITCH;        // KT * PITCH
    float* s_s   = zsm + KT * PITCH;        // KT
    float* s_t   = s_s + KT;                // KT
    float* s_x2  = s_t + KT;                // KT
    float* s_xa  = s_x2 + KT;               // KT
    float* s_an2 = s_xa + KT;               // KT
    float* s_y2  = s_an2 + KT;              // BT

    const int tid  = threadIdx.x;
    const int b0   = blockIdx.x * BT;
    const int k0   = blockIdx.y * KT;
    const int warp = tid >> 5;
    const int lane = tid & 31;

    // ---- load Y tile (BT x D) into smem, float4, coalesced ----
    {
        const int n4 = BT * (DD / 4);  // 4096
        #pragma unroll
        for (int idx = tid; idx < n4; idx += NTHREADS) {
            int row = idx >> 6;        // /64
            int c4  = idx & 63;
            float4 v = reinterpret_cast<const float4*>(Y + (size_t)(b0 + row) * DD)[c4];
            *reinterpret_cast<float4*>(&ysm[row * PITCH + c4 * 4]) = v;
        }
    }
    // ---- load Z tile (KT x D) ----
    {
        const int n4 = KT * (DD / 4);  // 2048
        #pragma unroll
        for (int idx = tid; idx < n4; idx += NTHREADS) {
            int row = idx >> 6;
            int c4  = idx & 63;
            float4 v = reinterpret_cast<const float4*>(Z + (size_t)(k0 + row) * DD)[c4];
            *reinterpret_cast<float4*>(&zsm[row * PITCH + c4 * 4]) = v;
        }
    }
    __syncthreads();

    // ---- per-k scalars: warp w handles rows w*4 .. w*4+3 ----
    #pragma unroll
    for (int rr = 0; rr < 4; rr++) {
        int row = warp * 4 + rr;
        const float* zr = zsm + row * PITCH;
        float sum = 0.f;
        #pragma unroll
        for (int i = 0; i < 8; i++) {
            float v = zr[lane + 32 * i];
            sum = fmaf(v, v, sum);
        }
        #pragma unroll
        for (int off = 16; off > 0; off >>= 1)
            sum += __shfl_xor_sync(0xffffffffu, sum, off);
        if (lane == 0) {
            float zn2 = sum;
            float zn  = sqrtf(zn2);
            float r   = R[k0 + row];
            float un  = fmaxf(fabsf(r) * zn, 1e-15f);
            float s   = -tanhf(un) * r / un;
            float th  = tanhf(r);
            float ic2 = 1.0f - th * th;      // 1/cosh(r)^2
            float an  = zn * ic2;
            float t   = ic2 / fmaxf(an, 1e-12f);
            s_s[row]   = s;
            s_t[row]   = t;
            s_x2[row]  = s * s * zn2;
            s_xa[row]  = s * zn2 * t;
            s_an2[row] = 2.0f * an;
        }
    }

    // ---- per-b y2: warp w handles rows w*8 .. w*8+7 ----
    #pragma unroll
    for (int rr = 0; rr < 8; rr++) {
        int row = warp * 8 + rr;
        const float* yr = ysm + row * PITCH;
        float sum = 0.f;
        #pragma unroll
        for (int i = 0; i < 8; i++) {
            float v = yr[lane + 32 * i];
            sum = fmaf(v, v, sum);
        }
        #pragma unroll
        for (int off = 16; off > 0; off >>= 1)
            sum += __shfl_xor_sync(0xffffffffu, sum, off);
        if (lane == 0) s_y2[row] = sum;
    }
    __syncthreads();

    // ---- main GEMM: 16x16 threads, each 4(b) x 2(k), float4 over D ----
    const int ty = tid >> 4;   // 0..15
    const int tx = tid & 15;   // 0..15

    float acc[4][2];
    #pragma unroll
    for (int i = 0; i < 4; i++) { acc[i][0] = 0.f; acc[i][1] = 0.f; }

    const float* yb = ysm + (ty * 4) * PITCH;
    const float* z0p = zsm + tx * PITCH;
    const float* z1p = zsm + (tx + 16) * PITCH;

    #pragma unroll 8
    for (int d4 = 0; d4 < DD / 4; d4++) {
        float4 z0 = *reinterpret_cast<const float4*>(&z0p[d4 * 4]);
        float4 z1 = *reinterpret_cast<const float4*>(&z1p[d4 * 4]);
        #pragma unroll
        for (int i = 0; i < 4; i++) {
            float4 yv = *reinterpret_cast<const float4*>(&yb[i * PITCH + d4 * 4]);
            acc[i][0] = fmaf(yv.x, z0.x, acc[i][0]);
            acc[i][0] = fmaf(yv.y, z0.y, acc[i][0]);
            acc[i][0] = fmaf(yv.z, z0.z, acc[i][0]);
            acc[i][0] = fmaf(yv.w, z0.w, acc[i][0]);
            acc[i][1] = fmaf(yv.x, z1.x, acc[i][1]);
            acc[i][1] = fmaf(yv.y, z1.y, acc[i][1]);
            acc[i][1] = fmaf(yv.z, z1.z, acc[i][1]);
            acc[i][1] = fmaf(yv.w, z1.w, acc[i][1]);
        }
    }

    // ---- epilogue ----
    #pragma unroll
    for (int j = 0; j < 2; j++) {
        int kl = tx + 16 * j;
        float s   = s_s[kl];
        float t   = s_t[kl];
        float x2  = s_x2[kl];
        float xa  = s_xa[kl];
        float an2 = s_an2[kl];
        float T   = 1.0f - x2;
        #pragma unroll
        for (int i = 0; i < 4; i++) {
            int bl = ty * 4 + i;
            float g  = acc[i][j];
            float y2 = s_y2[bl];
            float xy = s * g;
            float ya = t * g;
            float S   = fmaf(2.0f, xy, 1.0f) + y2;
            float den = fmaf(2.0f, xy, 1.0f) + x2 * y2;
            float P   = S * S * x2 + 2.0f * S * T * xy + T * T * y2;
            float v   = 2.0f * (S * xa + T * ya) * den / (den * den - P);
            Out[(size_t)(b0 + bl) * KK + (k0 + kl)] = an2 * asinhf(v);
        }
    }
}

extern "C" void kernel_launch(void* const* d_in, const int* in_sizes, int n_in,
                              void* d_out, int out_size)
{
    const float* Y = (const float*)d_in[0];   // output_before (2048, 256)
    const float* Z = (const float*)d_in[1];   // z_mlr (128, 256)
    const float* R = (const float*)d_in[2];   // mlr_r (128, 1)
    float* Out = (float*)d_out;               // (2048, 128)

    size_t shmem = (size_t)(BT * PITCH + KT * PITCH + 5 * KT + BT) * sizeof(float);
    cudaFuncSetAttribute(mlr_logits_kernel,
                         cudaFuncAttributeMaxDynamicSharedMemorySize, (int)shmem);

    dim3 grid(BB / BT, KK / KT);   // 32 x 4 = 128 blocks
    dim3 block(NTHREADS);
    mlr_logits_kernel<<<grid, block, shmem>>>(Y, Z, R, Out);
}